// round 2
// baseline (speedup 1.0000x reference)
#include <cuda_runtime.h>

#define B_  4
#define Qn  1024
#define Kn  1024
#define QS  256
#define KSZ 256
#define Hn  32
#define VD  256
#define TQ  8
#define TK  128

// Device-global scratch (no runtime allocation allowed)
__device__ float g_fq[B_ * Qn * Hn];
__device__ float g_fk[B_ * Kn * Hn];

// ---------------- helpers ----------------

__device__ __forceinline__ float fast_tanh(float x) {
    // Single-MUFU hardware tanh (sm_75+). abs err ~5e-4, fine vs 1e-3 budget.
    float y;
    asm("tanh.approx.f32 %0, %1;" : "=f"(y) : "f"(x));
    return y;
}

__device__ __forceinline__ float warp_max(float v) {
    #pragma unroll
    for (int o = 16; o > 0; o >>= 1) v = fmaxf(v, __shfl_xor_sync(0xFFFFFFFFu, v, o));
    return v;
}
__device__ __forceinline__ float warp_sum(float v) {
    #pragma unroll
    for (int o = 16; o > 0; o >>= 1) v += __shfl_xor_sync(0xFFFFFFFFu, v, o);
    return v;
}

__device__ __forceinline__ unsigned long long pack2(float lo, float hi) {
    unsigned long long r;
    asm("mov.b64 %0, {%1, %2};" : "=l"(r) : "f"(lo), "f"(hi));
    return r;
}
__device__ __forceinline__ void unpack2(unsigned long long a, float& lo, float& hi) {
    asm("mov.b64 {%0, %1}, %2;" : "=f"(lo), "=f"(hi) : "l"(a));
}
__device__ __forceinline__ void fma2(unsigned long long& a, unsigned long long v, unsigned long long p) {
    asm("fma.rn.f32x2 %0, %1, %2, %0;" : "+l"(a) : "l"(v), "l"(p));
}
__device__ __forceinline__ void mul2(unsigned long long& a, unsigned long long s) {
    asm("mul.rn.f32x2 %0, %0, %1;" : "+l"(a) : "l"(s));
}

// ---------------- kernel 1: projections fq = q@Wq+bq, fk = k@Wk+bk ----------------

__global__ __launch_bounds__(256)
void proj_kernel(const float* __restrict__ queries, const float* __restrict__ keys,
                 const float* __restrict__ Wq, const float* __restrict__ bq,
                 const float* __restrict__ Wk, const float* __restrict__ bk) {
    __shared__ float xs[8][QS];
    int w = threadIdx.x >> 5, lane = threadIdx.x & 31;
    int row = blockIdx.x * 8 + w;

    const float* src; const float* W; const float* bias; float* dst;
    if (row < B_ * Qn) {
        src = queries + (size_t)row * QS; W = Wq; bias = bq; dst = g_fq + (size_t)row * Hn;
    } else {
        int r2 = row - B_ * Qn;
        src = keys + (size_t)r2 * KSZ; W = Wk; bias = bk; dst = g_fk + (size_t)r2 * Hn;
    }

    #pragma unroll
    for (int r = 0; r < QS / 32; r++) xs[w][lane + 32 * r] = src[lane + 32 * r];
    __syncwarp();

    float sum = 0.0f;
    #pragma unroll 8
    for (int j = 0; j < QS; j++) sum = fmaf(xs[w][j], W[j * Hn + lane], sum);
    dst[lane] = sum + bias[lane];
}

// ---------------- kernel 2: fused additive attention ----------------
// grid = (Q/TQ, B), block = 256. Warp w: phase A owns q-row w; phase B owns k-slice w.

__global__ __launch_bounds__(256)
void attn_kernel(const float* __restrict__ values, const int* __restrict__ valid_lens,
                 const float* __restrict__ wvec, float* __restrict__ out) {
    __shared__ float fk_s[TK * 36];                // [k][h], row stride 36 floats -> conflict-free LDS.128
    __shared__ unsigned long long pT2[TK * 9];     // [k][q] as duplicated pair {p,p}, stride 9 (72B) -> conflict-free
    __shared__ float fq_s[TQ * 32];
    __shared__ float wv_s[32];
    __shared__ float scale_s[TQ];
    __shared__ float l_s[TQ];

    const int tid  = threadIdx.x;
    const int w    = tid >> 5;
    const int lane = tid & 31;
    const int b    = blockIdx.y;
    const int q0   = blockIdx.x * TQ;
    const int valid = valid_lens[b];

    fq_s[w * 32 + lane] = g_fq[((size_t)(b * Qn + q0 + w)) * Hn + lane];
    if (tid < 32) wv_s[tid] = wvec[tid];

    float m_run = -1e30f, l_run = 0.0f;
    unsigned long long acc[TQ][4];
    #pragma unroll
    for (int q = 0; q < TQ; q++)
        #pragma unroll
        for (int j = 0; j < 4; j++) acc[q][j] = 0ull;

    const float* vbatch = values + (size_t)b * Kn * VD;
    const int nchunks = (valid + TK - 1) / TK;

    for (int c = 0; c < nchunks; c++) {
        const int kb = c * TK;
        __syncthreads();  // prior-phase consumers of fk_s / pT2 are done

        // Load fk chunk: 1024 float4s, 4 per thread, coalesced LDG -> padded smem
        {
            const float4* src = (const float4*)(g_fk + ((size_t)(b * Kn + kb)) * Hn);
            float4* dstp = (float4*)fk_s;
            #pragma unroll
            for (int r = 0; r < 4; r++) {
                int idx = tid + 256 * r;
                int k = idx >> 3, hb = idx & 7;
                dstp[k * 9 + hb] = src[idx];
            }
        }
        __syncthreads();

        // -------- Phase A: scores for q=w, k=lane+32i (stay in registers) --------
        float sacc[4] = {0.f, 0.f, 0.f, 0.f};
        {
            const float4* fq4 = (const float4*)(fq_s + w * 32);
            const float4* wv4 = (const float4*)wv_s;
            const float4* fk4 = (const float4*)fk_s;
            #pragma unroll
            for (int hb = 0; hb < 8; hb++) {
                float4 a = fq4[hb];
                float4 g = wv4[hb];
                #pragma unroll
                for (int i = 0; i < 4; i++) {
                    float4 f = fk4[(lane + 32 * i) * 9 + hb];
                    sacc[i] = fmaf(g.x, fast_tanh(a.x + f.x), sacc[i]);
                    sacc[i] = fmaf(g.y, fast_tanh(a.y + f.y), sacc[i]);
                    sacc[i] = fmaf(g.z, fast_tanh(a.z + f.z), sacc[i]);
                    sacc[i] = fmaf(g.w, fast_tanh(a.w + f.w), sacc[i]);
                }
            }
            #pragma unroll
            for (int i = 0; i < 4; i++)
                if (kb + lane + 32 * i >= valid) sacc[i] = -1e30f;
        }

        // -------- Online softmax (per-warp, warp w owns row q=w) --------
        {
            float mx = fmaxf(fmaxf(sacc[0], sacc[1]), fmaxf(sacc[2], sacc[3]));
            mx = warp_max(mx);
            float m_new = fmaxf(m_run, mx);
            float sc = __expf(m_run - m_new);
            m_run = m_new;
            float ps = 0.0f;
            #pragma unroll
            for (int i = 0; i < 4; i++) {
                float p = __expf(sacc[i] - m_new);
                ps += p;
                pT2[(lane + 32 * i) * 9 + w] = pack2(p, p);
            }
            ps = warp_sum(ps);
            l_run = l_run * sc + ps;
            if (lane == 0) scale_s[w] = sc;
        }
        __syncthreads();

        // -------- Phase B: P@V. warp w = k-slice [w*16, w*16+16), lanes = v --------
        {
            #pragma unroll
            for (int q = 0; q < TQ; q++) {
                unsigned long long s2 = pack2(scale_s[q], scale_s[q]);
                #pragma unroll
                for (int j = 0; j < 4; j++) mul2(acc[q][j], s2);
            }
            const int kloc0 = w * 16;
            #pragma unroll 4
            for (int kk = 0; kk < 16; kk++) {
                int kg = kb + kloc0 + kk;
                if (kg >= valid) break;
                const ulonglong2* vrow = (const ulonglong2*)(vbatch + (size_t)kg * VD);
                ulonglong2 v0 = __ldg(&vrow[lane * 2]);
                ulonglong2 v1 = __ldg(&vrow[lane * 2 + 1]);
                const unsigned long long* prow = pT2 + (kloc0 + kk) * 9;
                #pragma unroll
                for (int q = 0; q < TQ; q++) {
                    unsigned long long p2 = prow[q];   // broadcast LDS.64, already duplicated
                    fma2(acc[q][0], v0.x, p2);
                    fma2(acc[q][1], v0.y, p2);
                    fma2(acc[q][2], v1.x, p2);
                    fma2(acc[q][3], v1.y, p2);
                }
            }
        }
    }

    // -------- Epilogue: reduce partial acc across the 8 k-slice warps --------
    if (lane == 0) l_s[w] = l_run;
    __syncthreads();

    float* buf = fk_s;  // reuse (4608 floats >= 2048)
    #pragma unroll
    for (int q = 0; q < TQ; q++) {
        #pragma unroll
        for (int j = 0; j < 4; j++) {
            float lo, hi;
            unpack2(acc[q][j], lo, hi);
            buf[w * 256 + lane * 8 + 2 * j]     = lo;
            buf[w * 256 + lane * 8 + 2 * j + 1] = hi;
        }
        __syncthreads();
        float tot = 0.0f;
        #pragma unroll
        for (int g = 0; g < 8; g++) tot += buf[g * 256 + tid];
        float inv = 1.0f / l_s[q];
        out[((size_t)(b * Qn + q0 + q)) * VD + tid] = tot * inv;
        __syncthreads();
    }
}

// ---------------- launch ----------------

extern "C" void kernel_launch(void* const* d_in, const int* in_sizes, int n_in,
                              void* d_out, int out_size) {
    const float* keys       = (const float*)d_in[0];
    const float* queries    = (const float*)d_in[1];
    const float* values     = (const float*)d_in[2];
    const int*   valid_lens = (const int*)d_in[3];
    const float* W_q        = (const float*)d_in[4];
    const float* b_q        = (const float*)d_in[5];
    const float* W_k        = (const float*)d_in[6];
    const float* b_k        = (const float*)d_in[7];
    const float* w_v        = (const float*)d_in[8];
    // b_v (d_in[9]) is softmax-invariant: adding a constant to all scores does
    // not change the softmax weights, so it is intentionally unused.
    float* out = (float*)d_out;

    int total_rows = B_ * (Qn + Kn);            // 8192
    proj_kernel<<<total_rows / 8, 256>>>(queries, keys, W_q, b_q, W_k, b_k);

    dim3 grid(Qn / TQ, B_);
    attn_kernel<<<grid, 256>>>(values, valid_lens, w_v, out);
}

// round 3
// speedup vs baseline: 1.3090x; 1.3090x over previous
#include <cuda_runtime.h>

#define B_  4
#define Qn  1024
#define Kn  1024
#define QS  256
#define KSZ 256
#define Hn  32
#define VD  256
#define TQ  8
#define TK  128

// Device-global scratch (no runtime allocation allowed)
__device__ float g_fq[B_ * Qn * Hn];
__device__ float g_fk[B_ * Kn * Hn];

// ---------------- helpers ----------------

__device__ __forceinline__ float fast_tanh(float x) {
    // Single-MUFU hardware tanh (sm_75+). abs err ~5e-4; observed end-to-end ~3e-6.
    float y;
    asm("tanh.approx.f32 %0, %1;" : "=f"(y) : "f"(x));
    return y;
}

__device__ __forceinline__ float warp_max(float v) {
    #pragma unroll
    for (int o = 16; o > 0; o >>= 1) v = fmaxf(v, __shfl_xor_sync(0xFFFFFFFFu, v, o));
    return v;
}
__device__ __forceinline__ float warp_sum(float v) {
    #pragma unroll
    for (int o = 16; o > 0; o >>= 1) v += __shfl_xor_sync(0xFFFFFFFFu, v, o);
    return v;
}

__device__ __forceinline__ unsigned long long pack2(float lo, float hi) {
    unsigned long long r;
    asm("mov.b64 %0, {%1, %2};" : "=l"(r) : "f"(lo), "f"(hi));
    return r;
}
__device__ __forceinline__ void unpack2(unsigned long long a, float& lo, float& hi) {
    asm("mov.b64 {%0, %1}, %2;" : "=f"(lo), "=f"(hi) : "l"(a));
}
__device__ __forceinline__ void fma2(unsigned long long& a, unsigned long long v, unsigned long long p) {
    asm("fma.rn.f32x2 %0, %1, %2, %0;" : "+l"(a) : "l"(v), "l"(p));
}
__device__ __forceinline__ void mul2(unsigned long long& a, unsigned long long s) {
    asm("mul.rn.f32x2 %0, %0, %1;" : "+l"(a) : "l"(s));
}

// ---------------- kernel 1: projections fq = q@Wq+bq, fk = k@Wk+bk ----------------

__global__ __launch_bounds__(256)
void proj_kernel(const float* __restrict__ queries, const float* __restrict__ keys,
                 const float* __restrict__ Wq, const float* __restrict__ bq,
                 const float* __restrict__ Wk, const float* __restrict__ bk) {
    __shared__ float xs[8][QS];
    int w = threadIdx.x >> 5, lane = threadIdx.x & 31;
    int row = blockIdx.x * 8 + w;

    const float* src; const float* W; const float* bias; float* dst;
    if (row < B_ * Qn) {
        src = queries + (size_t)row * QS; W = Wq; bias = bq; dst = g_fq + (size_t)row * Hn;
    } else {
        int r2 = row - B_ * Qn;
        src = keys + (size_t)r2 * KSZ; W = Wk; bias = bk; dst = g_fk + (size_t)r2 * Hn;
    }

    #pragma unroll
    for (int r = 0; r < QS / 32; r++) xs[w][lane + 32 * r] = src[lane + 32 * r];
    __syncwarp();

    float sum = 0.0f;
    #pragma unroll 8
    for (int j = 0; j < QS; j++) sum = fmaf(xs[w][j], W[j * Hn + lane], sum);
    dst[lane] = sum + bias[lane];
}

// ---------------- kernel 2: fused additive attention ----------------
// grid = (Q/TQ, B), block = 256. Warp w: phase A owns q-row w; phase B owns k-slice w.
// __launch_bounds__(256, 2) pins regs <= 128 so 2 CTAs/SM fit (R2 regression fix).

__global__ __launch_bounds__(256, 2)
void attn_kernel(const float* __restrict__ values, const int* __restrict__ valid_lens,
                 const float* __restrict__ wvec, float* __restrict__ out) {
    __shared__ float fk_s[TK * 36];                // [k][h], row stride 36 floats -> conflict-free LDS.128
    __shared__ unsigned long long pT2[TK * 9];     // [k][q] duplicated pair {p,p}, stride 9 (72B) -> conflict-free
    __shared__ float fq_s[TQ * 32];
    __shared__ float wv_s[32];
    __shared__ unsigned long long scale2_s[TQ];    // duplicated pair {sc,sc}
    __shared__ float l_s[TQ];

    const int tid  = threadIdx.x;
    const int w    = tid >> 5;
    const int lane = tid & 31;
    const int b    = blockIdx.y;
    const int q0   = blockIdx.x * TQ;
    const int valid = valid_lens[b];

    fq_s[w * 32 + lane] = g_fq[((size_t)(b * Qn + q0 + w)) * Hn + lane];
    if (tid < 32) wv_s[tid] = wvec[tid];

    float m_run = -1e30f, l_run = 0.0f;
    unsigned long long acc[TQ][4];
    #pragma unroll
    for (int q = 0; q < TQ; q++)
        #pragma unroll
        for (int j = 0; j < 4; j++) acc[q][j] = 0ull;

    const float* vbatch = values + (size_t)b * Kn * VD;
    const int nchunks = (valid + TK - 1) / TK;

    for (int c = 0; c < nchunks; c++) {
        const int kb = c * TK;
        __syncthreads();  // prior-phase consumers of fk_s / pT2 are done

        // Load fk chunk: 1024 float4s, 4 per thread, coalesced LDG -> padded smem
        {
            const float4* src = (const float4*)(g_fk + ((size_t)(b * Kn + kb)) * Hn);
            float4* dstp = (float4*)fk_s;
            #pragma unroll
            for (int r = 0; r < 4; r++) {
                int idx = tid + 256 * r;
                int k = idx >> 3, hb = idx & 7;
                dstp[k * 9 + hb] = src[idx];
            }
        }
        __syncthreads();

        // -------- Phase A: scores for q=w, k=lane+32i (stay in registers) --------
        float sacc[4] = {0.f, 0.f, 0.f, 0.f};
        {
            const float4* fq4 = (const float4*)(fq_s + w * 32);
            const float4* wv4 = (const float4*)wv_s;
            const float4* fk4 = (const float4*)fk_s;
            #pragma unroll
            for (int hb = 0; hb < 8; hb++) {
                float4 a = fq4[hb];
                float4 g = wv4[hb];
                #pragma unroll
                for (int i = 0; i < 4; i++) {
                    float4 f = fk4[(lane + 32 * i) * 9 + hb];
                    sacc[i] = fmaf(g.x, fast_tanh(a.x + f.x), sacc[i]);
                    sacc[i] = fmaf(g.y, fast_tanh(a.y + f.y), sacc[i]);
                    sacc[i] = fmaf(g.z, fast_tanh(a.z + f.z), sacc[i]);
                    sacc[i] = fmaf(g.w, fast_tanh(a.w + f.w), sacc[i]);
                }
            }
            #pragma unroll
            for (int i = 0; i < 4; i++)
                if (kb + lane + 32 * i >= valid) sacc[i] = -1e30f;
        }

        // -------- Online softmax (per-warp, warp w owns row q=w) --------
        {
            float mx = fmaxf(fmaxf(sacc[0], sacc[1]), fmaxf(sacc[2], sacc[3]));
            mx = warp_max(mx);
            float m_new = fmaxf(m_run, mx);
            float sc = __expf(m_run - m_new);
            m_run = m_new;
            float ps = 0.0f;
            #pragma unroll
            for (int i = 0; i < 4; i++) {
                float p = __expf(sacc[i] - m_new);
                ps += p;
                pT2[(lane + 32 * i) * 9 + w] = pack2(p, p);
            }
            ps = warp_sum(ps);
            l_run = l_run * sc + ps;
            if (lane == 0) scale2_s[w] = pack2(sc, sc);
        }
        __syncthreads();

        // -------- Phase B: P@V. warp w = k-slice [w*16, w*16+16), lanes = v --------
        {
            #pragma unroll
            for (int q = 0; q < TQ; q++) {
                unsigned long long s2 = scale2_s[q];
                #pragma unroll
                for (int j = 0; j < 4; j++) mul2(acc[q][j], s2);
            }
            const int kloc0 = w * 16;
            #pragma unroll 4
            for (int kk = 0; kk < 16; kk++) {
                int kg = kb + kloc0 + kk;
                if (kg >= valid) break;
                const ulonglong2* vrow = (const ulonglong2*)(vbatch + (size_t)kg * VD);
                ulonglong2 v0 = __ldg(&vrow[lane * 2]);
                ulonglong2 v1 = __ldg(&vrow[lane * 2 + 1]);
                const unsigned long long* prow = pT2 + (kloc0 + kk) * 9;
                #pragma unroll
                for (int q = 0; q < TQ; q++) {
                    unsigned long long p2 = prow[q];   // broadcast LDS.64, already duplicated
                    fma2(acc[q][0], v0.x, p2);
                    fma2(acc[q][1], v0.y, p2);
                    fma2(acc[q][2], v1.x, p2);
                    fma2(acc[q][3], v1.y, p2);
                }
            }
        }
    }

    // -------- Epilogue: reduce partial acc across the 8 k-slice warps --------
    if (lane == 0) l_s[w] = l_run;
    __syncthreads();

    float* buf = fk_s;  // reuse (4608 floats >= 2048)
    #pragma unroll
    for (int q = 0; q < TQ; q++) {
        #pragma unroll
        for (int j = 0; j < 4; j++) {
            float lo, hi;
            unpack2(acc[q][j], lo, hi);
            buf[w * 256 + lane * 8 + 2 * j]     = lo;
            buf[w * 256 + lane * 8 + 2 * j + 1] = hi;
        }
        __syncthreads();
        float tot = 0.0f;
        #pragma unroll
        for (int g = 0; g < 8; g++) tot += buf[g * 256 + tid];
        float inv = 1.0f / l_s[q];
        out[((size_t)(b * Qn + q0 + q)) * VD + tid] = tot * inv;
        __syncthreads();
    }
}

// ---------------- launch ----------------

extern "C" void kernel_launch(void* const* d_in, const int* in_sizes, int n_in,
                              void* d_out, int out_size) {
    const float* keys       = (const float*)d_in[0];
    const float* queries    = (const float*)d_in[1];
    const float* values     = (const float*)d_in[2];
    const int*   valid_lens = (const int*)d_in[3];
    const float* W_q        = (const float*)d_in[4];
    const float* b_q        = (const float*)d_in[5];
    const float* W_k        = (const float*)d_in[6];
    const float* b_k        = (const float*)d_in[7];
    const float* w_v        = (const float*)d_in[8];
    // b_v (d_in[9]) is softmax-invariant: adding a constant to all scores does
    // not change the softmax weights, so it is intentionally unused.
    float* out = (float*)d_out;

    int total_rows = B_ * (Qn + Kn);            // 8192
    proj_kernel<<<total_rows / 8, 256>>>(queries, keys, W_q, b_q, W_k, b_k);

    dim3 grid(Qn / TQ, B_);
    attn_kernel<<<grid, 256>>>(values, valid_lens, w_v, out);
}

// round 4
// speedup vs baseline: 1.3848x; 1.0579x over previous
#include <cuda_runtime.h>

#define B_  4
#define Qn  1024
#define Kn  1024
#define QS  256
#define KSZ 256
#define Hn  32
#define VD  256
#define TQ  8
#define TK  128

// Device-global scratch (no runtime allocation allowed)
__device__ float g_fq[B_ * Qn * Hn];
__device__ float g_fk[B_ * Kn * Hn];

// ---------------- helpers ----------------

__device__ __forceinline__ float fast_tanh(float x) {
    float y;
    asm("tanh.approx.f32 %0, %1;" : "=f"(y) : "f"(x));
    return y;
}

__device__ __forceinline__ float warp_sum(float v) {
    #pragma unroll
    for (int o = 16; o > 0; o >>= 1) v += __shfl_xor_sync(0xFFFFFFFFu, v, o);
    return v;
}

__device__ __forceinline__ unsigned long long pack2(float lo, float hi) {
    unsigned long long r;
    asm("mov.b64 %0, {%1, %2};" : "=l"(r) : "f"(lo), "f"(hi));
    return r;
}
__device__ __forceinline__ void unpack2(unsigned long long a, float& lo, float& hi) {
    asm("mov.b64 {%0, %1}, %2;" : "=f"(lo), "=f"(hi) : "l"(a));
}
__device__ __forceinline__ void fma2(unsigned long long& a, unsigned long long v, unsigned long long p) {
    asm("fma.rn.f32x2 %0, %1, %2, %0;" : "+l"(a) : "l"(v), "l"(p));
}

// ---------------- kernel 1: projections fq = q@Wq+bq, fk = k@Wk+bk ----------------

__global__ __launch_bounds__(256)
void proj_kernel(const float* __restrict__ queries, const float* __restrict__ keys,
                 const float* __restrict__ Wq, const float* __restrict__ bq,
                 const float* __restrict__ Wk, const float* __restrict__ bk) {
    __shared__ float xs[8][QS];
    int w = threadIdx.x >> 5, lane = threadIdx.x & 31;
    int row = blockIdx.x * 8 + w;

    const float* src; const float* W; const float* bias; float* dst;
    if (row < B_ * Qn) {
        src = queries + (size_t)row * QS; W = Wq; bias = bq; dst = g_fq + (size_t)row * Hn;
    } else {
        int r2 = row - B_ * Qn;
        src = keys + (size_t)r2 * KSZ; W = Wk; bias = bk; dst = g_fk + (size_t)r2 * Hn;
    }

    #pragma unroll
    for (int r = 0; r < QS / 32; r++) xs[w][lane + 32 * r] = src[lane + 32 * r];
    __syncwarp();

    float sum = 0.0f;
    #pragma unroll 8
    for (int j = 0; j < QS; j++) sum = fmaf(xs[w][j], W[j * Hn + lane], sum);
    dst[lane] = sum + bias[lane];
}

// ---------------- kernel 2: fused additive attention ----------------
// grid = (Q/TQ, B), block = 256. Warp w: phase A owns q-row w; phase B owns k-slice w.
// No online softmax: |score| <= ||w_v||_1 (~4.5 here) since |tanh|<=1, so exp()
// cannot overflow/underflow in fp32 and max-subtraction is unnecessary.
// Double-buffered fk_s/pT2 -> ONE barrier per chunk; fk prefetch hidden under phase A.

__global__ __launch_bounds__(256, 2)
void attn_kernel(const float* __restrict__ values, const int* __restrict__ valid_lens,
                 const float* __restrict__ wvec, float* __restrict__ out) {
    __shared__ float fk_s[2][TK * 36];               // [k][h], stride 36 floats -> conflict-free LDS.128
    __shared__ unsigned long long pT2[2][TK * 9];    // [k][q] duplicated pair {p,p}, stride 9 u64
    __shared__ float fq_s[TQ * 32];
    __shared__ float wv_s[32];
    __shared__ float l_s[TQ];

    const int tid  = threadIdx.x;
    const int w    = tid >> 5;
    const int lane = tid & 31;
    const int b    = blockIdx.y;
    const int q0   = blockIdx.x * TQ;
    const int valid = valid_lens[b];

    fq_s[w * 32 + lane] = g_fq[((size_t)(b * Qn + q0 + w)) * Hn + lane];
    if (tid < 32) wv_s[tid] = wvec[tid];

    float l_run = 0.0f;                 // per-lane partial row-sum for q=w
    unsigned long long acc[TQ][4];
    #pragma unroll
    for (int q = 0; q < TQ; q++)
        #pragma unroll
        for (int j = 0; j < 4; j++) acc[q][j] = 0ull;

    const float* vbatch = values + (size_t)b * Kn * VD;
    const int nchunks = (valid + TK - 1) / TK;

    // Preload chunk 0 into buffer 0
    {
        const float4* src = (const float4*)(g_fk + ((size_t)(b * Kn)) * Hn);
        float4* dstp = (float4*)fk_s[0];
        #pragma unroll
        for (int r = 0; r < 4; r++) {
            int idx = tid + 256 * r;
            dstp[(idx >> 3) * 9 + (idx & 7)] = __ldg(&src[idx]);
        }
    }
    __syncthreads();

    int buf = 0;
    for (int c = 0; c < nchunks; c++) {
        const int kb = c * TK;
        const bool full = (kb + TK <= valid);
        const bool has_next = (c + 1 < nchunks);

        // ---- Prefetch next fk chunk into registers (latency hidden by phase A) ----
        float4 pf0, pf1, pf2, pf3;
        if (has_next) {
            const float4* src = (const float4*)(g_fk + ((size_t)(b * Kn + kb + TK)) * Hn);
            pf0 = __ldg(&src[tid]);
            pf1 = __ldg(&src[tid + 256]);
            pf2 = __ldg(&src[tid + 512]);
            pf3 = __ldg(&src[tid + 768]);
        }

        // -------- Phase A: scores for q=w, k=lane+32i --------
        float sacc[4] = {0.f, 0.f, 0.f, 0.f};
        {
            const float4* fq4 = (const float4*)(fq_s + w * 32);
            const float4* wv4 = (const float4*)wv_s;
            const float4* fk4 = (const float4*)fk_s[buf];
            #pragma unroll
            for (int hb = 0; hb < 8; hb++) {
                float4 a = fq4[hb];
                float4 g = wv4[hb];
                #pragma unroll
                for (int i = 0; i < 4; i++) {
                    float4 f = fk4[(lane + 32 * i) * 9 + hb];
                    sacc[i] = fmaf(g.x, fast_tanh(a.x + f.x), sacc[i]);
                    sacc[i] = fmaf(g.y, fast_tanh(a.y + f.y), sacc[i]);
                    sacc[i] = fmaf(g.z, fast_tanh(a.z + f.z), sacc[i]);
                    sacc[i] = fmaf(g.w, fast_tanh(a.w + f.w), sacc[i]);
                }
            }
        }

        // -------- p = exp(score) (no max shift needed; scores bounded), mask, store --------
        if (full) {
            #pragma unroll
            for (int i = 0; i < 4; i++) {
                float p = __expf(sacc[i]);
                l_run += p;
                pT2[buf][(lane + 32 * i) * 9 + w] = pack2(p, p);
            }
        } else {
            #pragma unroll
            for (int i = 0; i < 4; i++) {
                float p = (kb + lane + 32 * i < valid) ? __expf(sacc[i]) : 0.0f;
                l_run += p;
                pT2[buf][(lane + 32 * i) * 9 + w] = pack2(p, p);
            }
        }

        // ---- Store prefetched chunk into the spare buffer ----
        if (has_next) {
            float4* dstp = (float4*)fk_s[buf ^ 1];
            dstp[((tid      ) >> 3) * 9 + ((tid      ) & 7)] = pf0;
            dstp[((tid + 256) >> 3) * 9 + ((tid + 256) & 7)] = pf1;
            dstp[((tid + 512) >> 3) * 9 + ((tid + 512) & 7)] = pf2;
            dstp[((tid + 768) >> 3) * 9 + ((tid + 768) & 7)] = pf3;
        }

        __syncthreads();   // pT2[buf] visible to all warps; fk_s[buf^1] ready for next A

        // -------- Phase B: P@V. warp w = k-slice [w*16, w*16+16), lanes = v --------
        {
            const int kloc0 = w * 16;
            const unsigned long long* pbase = pT2[buf] + kloc0 * 9;
            const float* vb = vbatch + (size_t)(kb + kloc0) * VD;
            if (full) {
                #pragma unroll 4
                for (int kk = 0; kk < 16; kk++) {
                    const ulonglong2* vrow = (const ulonglong2*)(vb + (size_t)kk * VD);
                    ulonglong2 v0 = __ldg(&vrow[lane * 2]);
                    ulonglong2 v1 = __ldg(&vrow[lane * 2 + 1]);
                    const unsigned long long* prow = pbase + kk * 9;
                    #pragma unroll
                    for (int q = 0; q < TQ; q++) {
                        unsigned long long p2 = prow[q];
                        fma2(acc[q][0], v0.x, p2);
                        fma2(acc[q][1], v0.y, p2);
                        fma2(acc[q][2], v1.x, p2);
                        fma2(acc[q][3], v1.y, p2);
                    }
                }
            } else {
                int rem = valid - kb - kloc0;           // may be <=0
                int kend = rem < 16 ? (rem < 0 ? 0 : rem) : 16;
                for (int kk = 0; kk < kend; kk++) {
                    const ulonglong2* vrow = (const ulonglong2*)(vb + (size_t)kk * VD);
                    ulonglong2 v0 = __ldg(&vrow[lane * 2]);
                    ulonglong2 v1 = __ldg(&vrow[lane * 2 + 1]);
                    const unsigned long long* prow = pbase + kk * 9;
                    #pragma unroll
                    for (int q = 0; q < TQ; q++) {
                        unsigned long long p2 = prow[q];
                        fma2(acc[q][0], v0.x, p2);
                        fma2(acc[q][1], v0.y, p2);
                        fma2(acc[q][2], v1.x, p2);
                        fma2(acc[q][3], v1.y, p2);
                    }
                }
            }
        }
        buf ^= 1;
    }

    // -------- Epilogue: row-sum l, then reduce partial acc across 8 warps --------
    float l = warp_sum(l_run);
    if (lane == 0) l_s[w] = l;
    __syncthreads();

    float* bufp = fk_s[0];  // reuse (4608 floats >= 2048)
    #pragma unroll
    for (int q = 0; q < TQ; q++) {
        #pragma unroll
        for (int j = 0; j < 4; j++) {
            float lo, hi;
            unpack2(acc[q][j], lo, hi);
            bufp[w * 256 + lane * 8 + 2 * j]     = lo;
            bufp[w * 256 + lane * 8 + 2 * j + 1] = hi;
        }
        __syncthreads();
        float tot = 0.0f;
        #pragma unroll
        for (int g = 0; g < 8; g++) tot += bufp[g * 256 + tid];
        float inv = 1.0f / l_s[q];
        out[((size_t)(b * Qn + q0 + q)) * VD + tid] = tot * inv;
        __syncthreads();
    }
}

// ---------------- launch ----------------

extern "C" void kernel_launch(void* const* d_in, const int* in_sizes, int n_in,
                              void* d_out, int out_size) {
    const float* keys       = (const float*)d_in[0];
    const float* queries    = (const float*)d_in[1];
    const float* values     = (const float*)d_in[2];
    const int*   valid_lens = (const int*)d_in[3];
    const float* W_q        = (const float*)d_in[4];
    const float* b_q        = (const float*)d_in[5];
    const float* W_k        = (const float*)d_in[6];
    const float* b_k        = (const float*)d_in[7];
    const float* w_v        = (const float*)d_in[8];
    // b_v (d_in[9]) is softmax-invariant and intentionally unused.
    float* out = (float*)d_out;

    int total_rows = B_ * (Qn + Kn);            // 8192
    proj_kernel<<<total_rows / 8, 256>>>(queries, keys, W_q, b_q, W_k, b_k);

    dim3 grid(Qn / TQ, B_);
    attn_kernel<<<grid, 256>>>(values, valid_lens, w_v, out);
}

// round 6
// speedup vs baseline: 1.4566x; 1.0518x over previous
#include <cuda_runtime.h>
#include <cstdint>

#define B_  4
#define Qn  1024
#define Kn  1024
#define QS  256
#define KSZ 256
#define Hn  32
#define VD  256
#define TQ  8
#define TK  128

// Device-global scratch (no runtime allocation allowed)
__device__ float g_fq[B_ * Qn * Hn];
__device__ float g_fk[B_ * Kn * Hn];

// ---------------- helpers ----------------

__device__ __forceinline__ float fast_tanh(float x) {
    float y;
    asm("tanh.approx.f32 %0, %1;" : "=f"(y) : "f"(x));
    return y;
}

__device__ __forceinline__ float warp_sum(float v) {
    #pragma unroll
    for (int o = 16; o > 0; o >>= 1) v += __shfl_xor_sync(0xFFFFFFFFu, v, o);
    return v;
}

__device__ __forceinline__ unsigned long long pack2(float lo, float hi) {
    unsigned long long r;
    asm("mov.b64 %0, {%1, %2};" : "=l"(r) : "f"(lo), "f"(hi));
    return r;
}
__device__ __forceinline__ void unpack2(unsigned long long a, float& lo, float& hi) {
    asm("mov.b64 {%0, %1}, %2;" : "=f"(lo), "=f"(hi) : "l"(a));
}
__device__ __forceinline__ void fma2(unsigned long long& a, unsigned long long v, unsigned long long p) {
    asm("fma.rn.f32x2 %0, %1, %2, %0;" : "+l"(a) : "l"(v), "l"(p));
}

__device__ __forceinline__ void cp_async16(unsigned int dst_smem, const void* src) {
    asm volatile("cp.async.ca.shared.global [%0], [%1], 16;" :: "r"(dst_smem), "l"(src));
}
__device__ __forceinline__ void cp_async_commit() {
    asm volatile("cp.async.commit_group;");
}
__device__ __forceinline__ void cp_async_wait0() {
    asm volatile("cp.async.wait_group 0;");
}

// ---------------- kernel 1: projections fq = q@Wq+bq, fk = k@Wk+bk ----------------

__global__ __launch_bounds__(256)
void proj_kernel(const float* __restrict__ queries, const float* __restrict__ keys,
                 const float* __restrict__ Wq, const float* __restrict__ bq,
                 const float* __restrict__ Wk, const float* __restrict__ bk,
                 const int* __restrict__ valid_lens) {
    __shared__ float xs[8][QS];
    int w = threadIdx.x >> 5, lane = threadIdx.x & 31;
    int row = blockIdx.x * 8 + w;

    const float* src; const float* W; const float* bias; float* dst;
    if (row < B_ * Qn) {
        src = queries + (size_t)row * QS; W = Wq; bias = bq; dst = g_fq + (size_t)row * Hn;
    } else {
        int r2 = row - B_ * Qn;
        // fk rows at/after valid_len are masked to p=0 in attn (never influence
        // the output), so skip their projection entirely.
        if ((r2 & (Kn - 1)) >= valid_lens[r2 >> 10]) return;
        src = keys + (size_t)r2 * KSZ; W = Wk; bias = bk; dst = g_fk + (size_t)r2 * Hn;
    }

    {
        const float4* s4 = (const float4*)src;
        float4* x4 = (float4*)xs[w];
        x4[lane]      = s4[lane];
        x4[lane + 32] = s4[lane + 32];
    }
    __syncwarp();

    float sum = 0.0f;
    #pragma unroll 8
    for (int j = 0; j < QS; j++) sum = fmaf(xs[w][j], W[j * Hn + lane], sum);
    dst[lane] = sum + bias[lane];
}

// ---------------- kernel 2: fused additive attention ----------------
// grid = (B, Q/TQ), block = 256 (8 warps), 3 CTAs/SM target (85 regs).
// Phase A: warp w = q-row w, lanes = k (4 per lane). No online softmax (scores
// bounded by ||w_v||_1 since |tanh|<=1 -> exp can't overflow in fp32).
// Phase B: warp w = (k-slice = (w>>1)*32, v-half = (w&1)*128); acc = 8q x 4f = 32 regs.
// Double-buffered fk_s (cp.async prefetch) + pT2; ONE barrier per chunk.

__global__ __launch_bounds__(256, 3)
void attn_kernel(const float* __restrict__ values, const int* __restrict__ valid_lens,
                 const float* __restrict__ wvec, float* __restrict__ out) {
    __shared__ float fk_s[2][TK * 36];                           // [k][h], stride 36 floats
    __shared__ __align__(16) unsigned long long pT2[2][TK * 10]; // [k][q] dup pair {p,p}, stride 10 u64
    __shared__ float fq_s[TQ * 32];
    __shared__ float wv_s[32];
    __shared__ float l_s[TQ];

    const int tid  = threadIdx.x;
    const int w    = tid >> 5;
    const int lane = tid & 31;
    const int b    = blockIdx.x;          // batch-interleaved across bid for wave balance
    const int q0   = blockIdx.y * TQ;
    const int valid = valid_lens[b];

    fq_s[w * 32 + lane] = g_fq[((size_t)(b * Qn + q0 + w)) * Hn + lane];
    if (tid < 32) wv_s[tid] = wvec[tid];

    float l_run = 0.0f;                   // per-lane partial row-sum for q=w
    unsigned long long acc[TQ][2];        // 8q x (4 floats of this warp's v-half)
    #pragma unroll
    for (int q = 0; q < TQ; q++) { acc[q][0] = 0ull; acc[q][1] = 0ull; }

    const float* vbatch = values + (size_t)b * Kn * VD;
    const int nchunks = (valid + TK - 1) / TK;

    // Preload chunk 0 into buffer 0 via cp.async
    {
        const float4* src = (const float4*)(g_fk + ((size_t)(b * Kn)) * Hn);
        #pragma unroll
        for (int r = 0; r < 4; r++) {
            int idx = tid + 256 * r;
            unsigned int dst = (unsigned int)__cvta_generic_to_shared(
                &((float4*)fk_s[0])[(idx >> 3) * 9 + (idx & 7)]);
            cp_async16(dst, &src[idx]);
        }
        cp_async_commit();
        cp_async_wait0();
    }
    __syncthreads();

    int buf = 0;
    for (int c = 0; c < nchunks; c++) {
        const int kb = c * TK;
        const bool full = (kb + TK <= valid);
        const bool has_next = (c + 1 < nchunks);

        // ---- Prefetch next fk chunk straight into the spare smem buffer ----
        if (has_next) {
            const float4* src = (const float4*)(g_fk + ((size_t)(b * Kn + kb + TK)) * Hn);
            #pragma unroll
            for (int r = 0; r < 4; r++) {
                int idx = tid + 256 * r;
                unsigned int dst = (unsigned int)__cvta_generic_to_shared(
                    &((float4*)fk_s[buf ^ 1])[(idx >> 3) * 9 + (idx & 7)]);
                cp_async16(dst, &src[idx]);
            }
            cp_async_commit();
        }

        // -------- Phase A: scores for q=w, k=lane+32i --------
        float sacc[4] = {0.f, 0.f, 0.f, 0.f};
        {
            const float4* fq4 = (const float4*)(fq_s + w * 32);
            const float4* wv4 = (const float4*)wv_s;
            const float4* fk4 = (const float4*)fk_s[buf];
            #pragma unroll
            for (int hb = 0; hb < 8; hb++) {
                float4 a = fq4[hb];
                float4 g = wv4[hb];
                #pragma unroll
                for (int i = 0; i < 4; i++) {
                    float4 f = fk4[(lane + 32 * i) * 9 + hb];
                    sacc[i] = fmaf(g.x, fast_tanh(a.x + f.x), sacc[i]);
                    sacc[i] = fmaf(g.y, fast_tanh(a.y + f.y), sacc[i]);
                    sacc[i] = fmaf(g.z, fast_tanh(a.z + f.z), sacc[i]);
                    sacc[i] = fmaf(g.w, fast_tanh(a.w + f.w), sacc[i]);
                }
            }
        }

        // -------- p = exp(score) (bounded, no max shift), mask, store dup-pair --------
        if (full) {
            #pragma unroll
            for (int i = 0; i < 4; i++) {
                float p = __expf(sacc[i]);
                l_run += p;
                pT2[buf][(lane + 32 * i) * 10 + w] = pack2(p, p);
            }
        } else {
            #pragma unroll
            for (int i = 0; i < 4; i++) {
                float p = (kb + lane + 32 * i < valid) ? __expf(sacc[i]) : 0.0f;
                l_run += p;
                pT2[buf][(lane + 32 * i) * 10 + w] = pack2(p, p);
            }
        }

        if (has_next) cp_async_wait0();
        __syncthreads();   // pT2[buf] visible; fk_s[buf^1] filled for next A

        // -------- Phase B: P@V. warp w = (k-slice (w>>1)*32, v-half (w&1)*128) --------
        {
            const int kloc0 = (w >> 1) * 32;
            const int voff  = (w & 1) * 128;
            const unsigned long long* pbase = pT2[buf] + kloc0 * 10;
            const float* vb = vbatch + (size_t)(kb + kloc0) * VD + voff;

            int kend;
            if (full) kend = 32;
            else { int rem = valid - kb - kloc0; kend = rem < 32 ? (rem < 0 ? 0 : rem) : 32; }

            #pragma unroll 4
            for (int kk = 0; kk < kend; kk++) {
                ulonglong2 v = __ldg((const ulonglong2*)(vb + (size_t)kk * VD) + lane);
                const ulonglong2* prow2 = (const ulonglong2*)(pbase + kk * 10);
                #pragma unroll
                for (int qp = 0; qp < 4; qp++) {
                    ulonglong2 pp = prow2[qp];       // broadcast LDS.128: {p[2qp],p[2qp]},{p[2qp+1],...}
                    fma2(acc[2 * qp][0],     v.x, pp.x);
                    fma2(acc[2 * qp][1],     v.y, pp.x);
                    fma2(acc[2 * qp + 1][0], v.x, pp.y);
                    fma2(acc[2 * qp + 1][1], v.y, pp.y);
                }
            }
        }
        buf ^= 1;
    }

    // -------- Epilogue: row-sums, then single-barrier cross-warp reduction --------
    float l = warp_sum(l_run);
    if (lane == 0) l_s[w] = l;

    // buf layout: [q][w][128] floats = 32KB, lives in fk_s (36KB)
    float* bufp = fk_s[0];
    #pragma unroll
    for (int q = 0; q < TQ; q++) {
        float f0, f1, f2, f3;
        unpack2(acc[q][0], f0, f1);
        unpack2(acc[q][1], f2, f3);
        float* d = bufp + (q * 8 + w) * 128 + lane * 4;
        d[0] = f0; d[1] = f1; d[2] = f2; d[3] = f3;
    }
    __syncthreads();

    // out element (q, v=tid): sum the 4 warps holding v-half (tid>>7)
    {
        const int vhalf = tid >> 7;
        const int idx   = tid & 127;
        const size_t obase = ((size_t)(b * Qn + q0)) * VD + tid;
        #pragma unroll
        for (int q = 0; q < TQ; q++) {
            const float* s = bufp + q * 1024 + vhalf * 128 + idx;
            float tot = s[0] + s[256] + s[512] + s[768];
            out[obase + (size_t)q * VD] = tot * (1.0f / l_s[q]);
        }
    }
}

// ---------------- launch ----------------

extern "C" void kernel_launch(void* const* d_in, const int* in_sizes, int n_in,
                              void* d_out, int out_size) {
    const float* keys       = (const float*)d_in[0];
    const float* queries    = (const float*)d_in[1];
    const float* values     = (const float*)d_in[2];
    const int*   valid_lens = (const int*)d_in[3];
    const float* W_q        = (const float*)d_in[4];
    const float* b_q        = (const float*)d_in[5];
    const float* W_k        = (const float*)d_in[6];
    const float* b_k        = (const float*)d_in[7];
    const float* w_v        = (const float*)d_in[8];
    // b_v (d_in[9]) is softmax-invariant and intentionally unused.
    float* out = (float*)d_out;

    int total_rows = B_ * (Qn + Kn);            // 8192
    proj_kernel<<<total_rows / 8, 256>>>(queries, keys, W_q, b_q, W_k, b_k, valid_lens);

    dim3 grid(B_, Qn / TQ);
    attn_kernel<<<grid, 256>>>(values, valid_lens, w_v, out);
}